// round 8
// baseline (speedup 1.0000x reference)
#include <cuda_runtime.h>
#include <math.h>
#include <stdint.h>

// ---------------------------------------------------------------------------
// Problem constants
// ---------------------------------------------------------------------------
#define BATCH   8
#define SEQ     2048
#define DIM     512
#define NTOK    (BATCH * SEQ)          // 16384

// GEMM tiling (mma.sync m16n8k8 tf32)
#define BM 128
#define BN 256
#define BK 32
#define NTHREADS 256                   // 8 warps, 2x4, 64x64 warp tiles
#define STAGES 3

// smem pitches (floats)
#define PA 36       // [rows][k] K-contiguous pitch (rows x 32 k)
#define PBN 264     // [k][n]  N-contiguous pitch  (32 k x 256 n)
#define SBUFA 4608  // 128*36
#define SBUFB 9216  // max(256*36=9216, 32*264=8448)
#define STAGE_F (SBUFA + SBUFB)
#define SMEM_BYTES_G (STAGES * STAGE_F * 4)   // 165888 B

// Epilogue tags
#define EPI_GATE     0
#define EPI_SCALE    1
#define EPI_ADD      2
#define EPI_GELU     3
#define EPI_BIAS_RES 4

// ---------------------------------------------------------------------------
// Scratch (device globals: allocation-free rule)
// ---------------------------------------------------------------------------
__device__ float g_fused [(size_t)NTOK * DIM];
__device__ float g_scores[(size_t)BATCH * SEQ * SEQ];
__device__ float g_q     [(size_t)NTOK * DIM];
__device__ float g_h     [(size_t)NTOK * 2 * DIM];
__device__ float g_y     [(size_t)NTOK * DIM];

// ---------------------------------------------------------------------------
// PTX helpers
// ---------------------------------------------------------------------------
__device__ __forceinline__ uint32_t smem_u32(const void* p) {
    uint32_t a;
    asm("{ .reg .u64 t; cvta.to.shared.u64 t, %1; cvt.u32.u64 %0, t; }" : "=r"(a) : "l"(p));
    return a;
}
__device__ __forceinline__ void cp16(uint32_t saddr, const void* gaddr) {
    asm volatile("cp.async.cg.shared.global [%0], [%1], 16;" :: "r"(saddr), "l"(gaddr));
}
__device__ __forceinline__ void cp_commit() {
    asm volatile("cp.async.commit_group;" ::: "memory");
}
template<int N>
__device__ __forceinline__ void cp_wait() {
    asm volatile("cp.async.wait_group %0;" :: "n"(N) : "memory");
}
__device__ __forceinline__ void mma_tf32(float* c, uint32_t a0, uint32_t a1,
                                         uint32_t a2, uint32_t a3,
                                         uint32_t b0, uint32_t b1) {
    asm volatile("mma.sync.aligned.m16n8k8.row.col.f32.tf32.tf32.f32 "
                 "{%0,%1,%2,%3}, {%4,%5,%6,%7}, {%8,%9}, {%0,%1,%2,%3};"
                 : "+f"(c[0]), "+f"(c[1]), "+f"(c[2]), "+f"(c[3])
                 : "r"(a0), "r"(a1), "r"(a2), "r"(a3), "r"(b0), "r"(b1));
}
__device__ __forceinline__ uint32_t ldsf(const float* p) {
    return __float_as_uint(*p);
}

// ---------------------------------------------------------------------------
// tf32 tensor-core GEMM: C[M,N] = A[M,K] * B  (B [N,K] if TB, [K,N] if !TB)
// 128x256x32 CTA tile, 8 warps (2x4), 64x64 warp tiles,
// 3-stage cp.async ring, 1 barrier per K-iter.
// If SPLITA: A columns [0,512) come from A, [512,1024) from A2 (virtual concat).
// ---------------------------------------------------------------------------
template<int EPI, bool TB, bool SPLITA>
__global__ void __launch_bounds__(NTHREADS, 1)
gemm_mma(const float* __restrict__ A, const float* __restrict__ A2,
         const float* __restrict__ B,
         float* __restrict__ C,
         int K, int lda, int ldb, int ldc,
         size_t strA, size_t strB, size_t strC,
         const float* __restrict__ bias,
         const float* __restrict__ res0,
         const float* __restrict__ res1,
         float scale)
{
    extern __shared__ float dsm[];

    const int z = blockIdx.z;
    A += (size_t)z * strA;
    B += (size_t)z * strB;
    C += (size_t)z * strC;
    if (res0) res0 += (size_t)z * strC;
    if (res1) res1 += (size_t)z * strC;

    const int bm   = blockIdx.y * BM;
    const int bn   = blockIdx.x * BN;
    const int tid  = threadIdx.x;
    const int wid  = tid >> 5;
    const int lane = tid & 31;
    const int warp_m = wid & 1;        // 0..1 -> 64 rows
    const int warp_n = wid >> 1;       // 0..3 -> 64 cols
    const int g  = lane >> 2;          // 0..7
    const int tg = lane & 3;           // 0..3

    const uint32_t smB = smem_u32(dsm);

    float acc[4][8][4];
    #pragma unroll
    for (int i = 0; i < 4; i++)
        #pragma unroll
        for (int j = 0; j < 8; j++)
            #pragma unroll
            for (int e = 0; e < 4; e++) acc[i][j][e] = 0.f;

    const int nit = K / BK;

    // ---- prefetch: one K=32 tile into stage it%STAGES ----
    auto prefetch = [&](int it) {
        const int kk = it * BK;
        const int st = it % STAGES;
        const uint32_t sa = smB + (uint32_t)(st * STAGE_F) * 4u;
        const uint32_t sb = sa + (uint32_t)SBUFA * 4u;
        // A: 128 rows x 8 float4 = 1024 chunks
        #pragma unroll
        for (int t = 0; t < 4; t++) {
            int id = tid + t * NTHREADS;       // 0..1023
            int r  = id >> 3;                  // 0..127
            int c4 = id & 7;                   // 0..7 (float4)
            int col = kk + c4 * 4;
            const float* src;
            if (SPLITA) {
                src = (col < DIM) ? (A  + (size_t)(bm + r) * DIM + col)
                                  : (A2 + (size_t)(bm + r) * DIM + (col - DIM));
            } else {
                src = A + (size_t)(bm + r) * lda + col;
            }
            cp16(sa + (uint32_t)(r * PA + c4 * 4) * 4u, src);
        }
        if (TB) {
            // B [N,K]: 256 n-rows x 8 float4 = 2048 chunks
            #pragma unroll
            for (int t = 0; t < 8; t++) {
                int id = tid + t * NTHREADS;
                int r  = id >> 3;              // n row 0..255
                int c4 = id & 7;
                cp16(sb + (uint32_t)(r * PA + c4 * 4) * 4u,
                     B + (size_t)(bn + r) * ldb + kk + c4 * 4);
            }
        } else {
            // B [K,N]: 32 k-rows x 64 float4 = 2048 chunks
            #pragma unroll
            for (int t = 0; t < 8; t++) {
                int id = tid + t * NTHREADS;
                int r  = id >> 6;              // k row 0..31
                int c4 = id & 63;              // 0..63
                cp16(sb + (uint32_t)(r * PBN + c4 * 4) * 4u,
                     B + (size_t)(kk + r) * ldb + bn + c4 * 4);
            }
        }
        cp_commit();
    };

    // prologue: fill 2 stages
    prefetch(0);
    prefetch(1);

    #pragma unroll 1
    for (int it = 0; it < nit; it++) {
        cp_wait<1>();          // group 'it' complete (it+1 may be in flight)
        __syncthreads();       // data visible; stage (it-1) fully consumed
        if (it + 2 < nit) prefetch(it + 2);   // writes stage (it-1)%3: safe

        const int st = it % STAGES;
        const float* Asb = dsm + st * STAGE_F;
        const float* Bsb = Asb + SBUFA;

        #pragma unroll
        for (int ks = 0; ks < 4; ks++) {
            const int kc = ks * 8;
            uint32_t af[4][4];
            #pragma unroll
            for (int mt = 0; mt < 4; mt++) {
                int m = warp_m * 64 + mt * 16;
                const float* ap = &Asb[(m + g) * PA + kc + tg];
                af[mt][0] = ldsf(ap);
                af[mt][1] = ldsf(ap + 8 * PA);
                af[mt][2] = ldsf(ap + 4);
                af[mt][3] = ldsf(ap + 8 * PA + 4);
            }
            uint32_t bf[8][2];
            #pragma unroll
            for (int nt = 0; nt < 8; nt++) {
                int n = warp_n * 64 + nt * 8;
                if (TB) {
                    const float* bp = &Bsb[(n + g) * PA + kc + tg];
                    bf[nt][0] = ldsf(bp);
                    bf[nt][1] = ldsf(bp + 4);
                } else {
                    const float* bp = &Bsb[(kc + tg) * PBN + n + g];
                    bf[nt][0] = ldsf(bp);
                    bf[nt][1] = ldsf(bp + 4 * PBN);
                }
            }
            #pragma unroll
            for (int mt = 0; mt < 4; mt++)
                #pragma unroll
                for (int nt = 0; nt < 8; nt++)
                    mma_tf32(acc[mt][nt], af[mt][0], af[mt][1], af[mt][2], af[mt][3],
                             bf[nt][0], bf[nt][1]);
        }
    }

    // ---- epilogue ----
    #pragma unroll
    for (int mt = 0; mt < 4; mt++) {
        #pragma unroll
        for (int nt = 0; nt < 8; nt++) {
            int r0 = bm + warp_m * 64 + mt * 16 + g;
            int cc = bn + warp_n * 64 + nt * 8 + tg * 2;
            #pragma unroll
            for (int half = 0; half < 2; half++) {
                int r = r0 + half * 8;
                float v0 = acc[mt][nt][half * 2 + 0];
                float v1 = acc[mt][nt][half * 2 + 1];
                size_t gix = (size_t)r * ldc + cc;
                float o0, o1;
                if (EPI == EPI_GATE) {
                    float gt0 = 1.f / (1.f + expf(-(v0 + bias[cc])));
                    float gt1 = 1.f / (1.f + expf(-(v1 + bias[cc + 1])));
                    o0 = gt0 * res0[gix]     + (1.f - gt0) * res1[gix];
                    o1 = gt1 * res0[gix + 1] + (1.f - gt1) * res1[gix + 1];
                } else if (EPI == EPI_SCALE) {
                    o0 = v0 * scale; o1 = v1 * scale;
                } else if (EPI == EPI_ADD) {
                    o0 = v0 + res0[gix]; o1 = v1 + res0[gix + 1];
                } else if (EPI == EPI_GELU) {
                    float x0 = v0 + bias[cc], x1 = v1 + bias[cc + 1];
                    o0 = 0.5f * x0 * (1.f + erff(x0 * 0.70710678118654752440f));
                    o1 = 0.5f * x1 * (1.f + erff(x1 * 0.70710678118654752440f));
                } else { // EPI_BIAS_RES
                    o0 = v0 + bias[cc]     + res0[gix];
                    o1 = v1 + bias[cc + 1] + res0[gix + 1];
                }
                *reinterpret_cast<float2*>(&C[gix]) = make_float2(o0, o1);
            }
        }
    }
}

// ---------------------------------------------------------------------------
// Warp helpers
// ---------------------------------------------------------------------------
__device__ __forceinline__ float warpMax(float v) {
    #pragma unroll
    for (int o = 16; o > 0; o >>= 1) v = fmaxf(v, __shfl_xor_sync(0xffffffffu, v, o));
    return v;
}
__device__ __forceinline__ float warpSum(float v) {
    #pragma unroll
    for (int o = 16; o > 0; o >>= 1) v += __shfl_xor_sync(0xffffffffu, v, o);
    return v;
}

// ---------------------------------------------------------------------------
// Row softmax over 2048 cols, in place
// ---------------------------------------------------------------------------
__global__ void __launch_bounds__(256)
softmax_kernel(float* __restrict__ S)
{
    float* p = S + (size_t)blockIdx.x * SEQ;
    const int tid  = threadIdx.x;
    const int lane = tid & 31;
    const int wid  = tid >> 5;
    __shared__ float sh[8];

    float v[8];
    *reinterpret_cast<float4*>(&v[0]) = *reinterpret_cast<const float4*>(&p[tid * 8]);
    *reinterpret_cast<float4*>(&v[4]) = *reinterpret_cast<const float4*>(&p[tid * 8 + 4]);

    float m = v[0];
    #pragma unroll
    for (int i = 1; i < 8; i++) m = fmaxf(m, v[i]);
    m = warpMax(m);
    if (lane == 0) sh[wid] = m;
    __syncthreads();
    m = sh[0];
    #pragma unroll
    for (int w = 1; w < 8; w++) m = fmaxf(m, sh[w]);
    __syncthreads();

    float s = 0.f;
    #pragma unroll
    for (int i = 0; i < 8; i++) { v[i] = expf(v[i] - m); s += v[i]; }
    s = warpSum(s);
    if (lane == 0) sh[wid] = s;
    __syncthreads();
    float tot = sh[0];
    #pragma unroll
    for (int w = 1; w < 8; w++) tot += sh[w];
    float inv = 1.f / tot;

    #pragma unroll
    for (int i = 0; i < 8; i++) v[i] *= inv;
    *reinterpret_cast<float4*>(&p[tid * 8])     = *reinterpret_cast<float4*>(&v[0]);
    *reinterpret_cast<float4*>(&p[tid * 8 + 4]) = *reinterpret_cast<float4*>(&v[4]);
}

// ---------------------------------------------------------------------------
// LayerNorm over last dim (512)
// ---------------------------------------------------------------------------
__global__ void __launch_bounds__(128)
layernorm_kernel(const float* __restrict__ in, float* __restrict__ out,
                 const float* __restrict__ gamma, const float* __restrict__ beta)
{
    const size_t base = (size_t)blockIdx.x * DIM;
    const int tid  = threadIdx.x;
    const int lane = tid & 31;
    const int wid  = tid >> 5;
    __shared__ float shs[4], shq[4];

    float4 x = *reinterpret_cast<const float4*>(&in[base + tid * 4]);
    float s  = x.x + x.y + x.z + x.w;
    float ss = x.x * x.x + x.y * x.y + x.z * x.z + x.w * x.w;
    s  = warpSum(s);
    ss = warpSum(ss);
    if (lane == 0) { shs[wid] = s; shq[wid] = ss; }
    __syncthreads();
    float sum = shs[0] + shs[1] + shs[2] + shs[3];
    float sq  = shq[0] + shq[1] + shq[2] + shq[3];
    float mu  = sum * (1.f / DIM);
    float var = sq * (1.f / DIM) - mu * mu;
    float rs  = rsqrtf(var + 1e-5f);

    float4 gm = *reinterpret_cast<const float4*>(&gamma[tid * 4]);
    float4 bt = *reinterpret_cast<const float4*>(&beta[tid * 4]);
    float4 o;
    o.x = (x.x - mu) * rs * gm.x + bt.x;
    o.y = (x.y - mu) * rs * gm.y + bt.y;
    o.z = (x.z - mu) * rs * gm.z + bt.z;
    o.w = (x.w - mu) * rs * gm.w + bt.w;
    *reinterpret_cast<float4*>(&out[base + tid * 4]) = o;
}

// ---------------------------------------------------------------------------
// Launch
// ---------------------------------------------------------------------------
extern "C" void kernel_launch(void* const* d_in, const int* in_sizes, int n_in,
                              void* d_out, int out_size)
{
    const float* Noise = (const float*)d_in[0];
    const float* X     = (const float*)d_in[1];
    const float* cond  = (const float*)d_in[2];
    const float* Wg    = (const float*)d_in[3];
    const float* bg    = (const float*)d_in[4];
    const float* W1    = (const float*)d_in[5];
    const float* b1    = (const float*)d_in[6];
    const float* W2    = (const float*)d_in[7];
    const float* b2    = (const float*)d_in[8];
    const float* g1    = (const float*)d_in[9];
    const float* be1   = (const float*)d_in[10];
    const float* g2    = (const float*)d_in[11];
    const float* be2   = (const float*)d_in[12];
    float* out = (float*)d_out;

    float *fused, *scores, *q, *h, *y;
    cudaGetSymbolAddress((void**)&fused,  g_fused);
    cudaGetSymbolAddress((void**)&scores, g_scores);
    cudaGetSymbolAddress((void**)&q,      g_q);
    cudaGetSymbolAddress((void**)&h,      g_h);
    cudaGetSymbolAddress((void**)&y,      g_y);

    cudaFuncSetAttribute(gemm_mma<EPI_GATE, false, true>,      cudaFuncAttributeMaxDynamicSharedMemorySize, SMEM_BYTES_G);
    cudaFuncSetAttribute(gemm_mma<EPI_SCALE, true, false>,     cudaFuncAttributeMaxDynamicSharedMemorySize, SMEM_BYTES_G);
    cudaFuncSetAttribute(gemm_mma<EPI_ADD, false, false>,      cudaFuncAttributeMaxDynamicSharedMemorySize, SMEM_BYTES_G);
    cudaFuncSetAttribute(gemm_mma<EPI_GELU, false, false>,     cudaFuncAttributeMaxDynamicSharedMemorySize, SMEM_BYTES_G);
    cudaFuncSetAttribute(gemm_mma<EPI_BIAS_RES, false, false>, cudaFuncAttributeMaxDynamicSharedMemorySize, SMEM_BYTES_G);

    const float scale = 0.04419417382415922f;  // 1/sqrt(512)

    // 1. gate = sigmoid(concat(Noise,cond) @ Wg + bg); fused = gate*Noise + (1-gate)*cond
    gemm_mma<EPI_GATE, false, true><<<dim3(DIM / BN, NTOK / BM, 1), NTHREADS, SMEM_BYTES_G>>>(
        Noise, cond, Wg, fused,
        2 * DIM, 2 * DIM, DIM, DIM,
        0, 0, 0, bg, Noise, cond, 0.f);

    // 2. scores = fused @ X^T * scale  (batched NT)
    gemm_mma<EPI_SCALE, true, false><<<dim3(SEQ / BN, SEQ / BM, BATCH), NTHREADS, SMEM_BYTES_G>>>(
        fused, nullptr, X, scores,
        DIM, DIM, DIM, SEQ,
        (size_t)SEQ * DIM, (size_t)SEQ * DIM, (size_t)SEQ * SEQ,
        nullptr, nullptr, nullptr, scale);

    // 3. softmax (in place)
    softmax_kernel<<<NTOK, 256>>>(scores);

    // 4. fused += attn @ X  (batched NN)
    gemm_mma<EPI_ADD, false, false><<<dim3(DIM / BN, SEQ / BM, BATCH), NTHREADS, SMEM_BYTES_G>>>(
        scores, nullptr, X, fused,
        SEQ, SEQ, DIM, DIM,
        (size_t)SEQ * SEQ, (size_t)SEQ * DIM, (size_t)SEQ * DIM,
        nullptr, fused, nullptr, 0.f);

    // 5. q = LN1(fused)
    layernorm_kernel<<<NTOK, 128>>>(fused, q, g1, be1);

    // 6. h = gelu(q @ W1 + b1)
    gemm_mma<EPI_GELU, false, false><<<dim3(2 * DIM / BN, NTOK / BM, 1), NTHREADS, SMEM_BYTES_G>>>(
        q, nullptr, W1, h,
        DIM, DIM, 2 * DIM, 2 * DIM,
        0, 0, 0, b1, nullptr, nullptr, 0.f);

    // 7. y = h @ W2 + b2 + q
    gemm_mma<EPI_BIAS_RES, false, false><<<dim3(DIM / BN, NTOK / BM, 1), NTHREADS, SMEM_BYTES_G>>>(
        h, nullptr, W2, y,
        2 * DIM, 2 * DIM, DIM, DIM,
        0, 0, 0, b2, q, nullptr, 0.f);

    // 8. out = LN2(y)
    layernorm_kernel<<<NTOK, 128>>>(y, out, g2, be2);
}

// round 9
// speedup vs baseline: 1.0715x; 1.0715x over previous
#include <cuda_runtime.h>
#include <math.h>
#include <stdint.h>

// ---------------------------------------------------------------------------
// Problem constants
// ---------------------------------------------------------------------------
#define BATCH   8
#define SEQ     2048
#define DIM     512
#define NTOK    (BATCH * SEQ)          // 16384

// GEMM tiling (mma.sync m16n8k8 tf32)
#define BM 128
#define BN 128
#define BK 32
#define NTHREADS 256                   // 8 warps, 2x4, 64x32 warp tiles
#define STAGES 3

// smem pitch (floats): K-contiguous rows, 32 k + 4 pad
#define PA 36
#define SBUFA 4608  // 128*36
#define SBUFB 4608  // 128*36
#define STAGE_F (SBUFA + SBUFB)
#define SMEM_BYTES_G (STAGES * STAGE_F * 4)   // 110592 B -> 2 CTAs/SM

// Epilogue tags
#define EPI_GATE     0
#define EPI_SCALE    1
#define EPI_ADD      2
#define EPI_GELU     3
#define EPI_BIAS_RES 4

// ---------------------------------------------------------------------------
// Scratch (device globals: allocation-free rule)
// ---------------------------------------------------------------------------
__device__ float g_fused [(size_t)NTOK * DIM];
__device__ float g_scores[(size_t)BATCH * SEQ * SEQ];
__device__ float g_q     [(size_t)NTOK * DIM];
__device__ float g_h     [(size_t)NTOK * 2 * DIM];
__device__ float g_y     [(size_t)NTOK * DIM];
__device__ float g_xt    [(size_t)BATCH * DIM * SEQ];   // X^T per batch [D,S]
__device__ float g_wgt   [(size_t)DIM * 2 * DIM];       // Wg^T [D, 2D]
__device__ float g_w1t   [(size_t)2 * DIM * DIM];       // W1^T [2D, D]
__device__ float g_w2t   [(size_t)DIM * 2 * DIM];       // W2^T [D, 2D]

// ---------------------------------------------------------------------------
// PTX helpers
// ---------------------------------------------------------------------------
__device__ __forceinline__ uint32_t smem_u32(const void* p) {
    uint32_t a;
    asm("{ .reg .u64 t; cvta.to.shared.u64 t, %1; cvt.u32.u64 %0, t; }" : "=r"(a) : "l"(p));
    return a;
}
__device__ __forceinline__ void cp16(uint32_t saddr, const void* gaddr) {
    asm volatile("cp.async.cg.shared.global [%0], [%1], 16;" :: "r"(saddr), "l"(gaddr));
}
__device__ __forceinline__ void cp_commit() {
    asm volatile("cp.async.commit_group;" ::: "memory");
}
template<int N>
__device__ __forceinline__ void cp_wait() {
    asm volatile("cp.async.wait_group %0;" :: "n"(N) : "memory");
}
__device__ __forceinline__ void mma_tf32(float* c, uint32_t a0, uint32_t a1,
                                         uint32_t a2, uint32_t a3,
                                         uint32_t b0, uint32_t b1) {
    asm volatile("mma.sync.aligned.m16n8k8.row.col.f32.tf32.tf32.f32 "
                 "{%0,%1,%2,%3}, {%4,%5,%6,%7}, {%8,%9}, {%0,%1,%2,%3};"
                 : "+f"(c[0]), "+f"(c[1]), "+f"(c[2]), "+f"(c[3])
                 : "r"(a0), "r"(a1), "r"(a2), "r"(a3), "r"(b0), "r"(b1));
}
__device__ __forceinline__ void ldsm4(uint32_t& r0, uint32_t& r1, uint32_t& r2,
                                      uint32_t& r3, uint32_t addr) {
    asm volatile("ldmatrix.sync.aligned.m8n8.x4.shared.b16 {%0,%1,%2,%3}, [%4];"
                 : "=r"(r0), "=r"(r1), "=r"(r2), "=r"(r3) : "r"(addr));
}

// ---------------------------------------------------------------------------
// tf32 tensor-core GEMM: C[M,N] = A[M,K] * B^T, B stored [N,K] (K-contiguous).
// 128x128x32 CTA tile, 8 warps (2x4), 64x32 warp tiles, ldmatrix fragments,
// 3-stage cp.async ring, 1 barrier per K-iter.
// If SPLITA: A columns [0,512) from A, [512,1024) from A2 (virtual concat).
// ---------------------------------------------------------------------------
template<int EPI, bool SPLITA>
__global__ void __launch_bounds__(NTHREADS, 2)
gemm_mma(const float* __restrict__ A, const float* __restrict__ A2,
         const float* __restrict__ B,
         float* __restrict__ C,
         int K, int lda, int ldb, int ldc,
         size_t strA, size_t strB, size_t strC,
         const float* __restrict__ bias,
         const float* __restrict__ res0,
         const float* __restrict__ res1,
         float scale)
{
    extern __shared__ float dsm[];

    const int z = blockIdx.z;
    A += (size_t)z * strA;
    B += (size_t)z * strB;
    C += (size_t)z * strC;
    if (res0) res0 += (size_t)z * strC;
    if (res1) res1 += (size_t)z * strC;

    const int bm   = blockIdx.y * BM;
    const int bn   = blockIdx.x * BN;
    const int tid  = threadIdx.x;
    const int wid  = tid >> 5;
    const int lane = tid & 31;
    const int warp_m = wid & 1;        // 0..1 -> 64 rows
    const int warp_n = wid >> 1;       // 0..3 -> 32 cols
    const int g  = lane >> 2;          // 0..7
    const int tg = lane & 3;           // 0..3
    const int quad  = lane >> 3;       // 0..3 (ldmatrix address groups)
    const int rowin = lane & 7;        // 0..7

    // ldmatrix per-lane row/col offsets
    const int a_row = (quad & 1) * 8 + rowin;   // A: matrices {rows, rows+8} x {kc, kc+4}
    const int a_col = (quad >> 1) * 4;
    const int b_row = (quad >> 1) * 8 + rowin;  // B: matrices {kc, kc+4} x {n, n+8}
    const int b_col = (quad & 1) * 4;

    const uint32_t smB = smem_u32(dsm);

    float acc[4][4][4];
    #pragma unroll
    for (int i = 0; i < 4; i++)
        #pragma unroll
        for (int j = 0; j < 4; j++)
            #pragma unroll
            for (int e = 0; e < 4; e++) acc[i][j][e] = 0.f;

    const int nit = K / BK;

    // ---- prefetch: one K=32 tile into stage it%STAGES (both operands TB) ----
    auto prefetch = [&](int it) {
        const int kk = it * BK;
        const int st = it % STAGES;
        const uint32_t sa = smB + (uint32_t)(st * STAGE_F) * 4u;
        const uint32_t sb = sa + (uint32_t)SBUFA * 4u;
        #pragma unroll
        for (int t = 0; t < 4; t++) {
            int id = tid + t * NTHREADS;       // 0..1023
            int r  = id >> 3;                  // 0..127
            int c4 = id & 7;                   // 0..7 (float4)
            int col = kk + c4 * 4;
            const float* src;
            if (SPLITA) {
                src = (col < DIM) ? (A  + (size_t)(bm + r) * DIM + col)
                                  : (A2 + (size_t)(bm + r) * DIM + (col - DIM));
            } else {
                src = A + (size_t)(bm + r) * lda + col;
            }
            cp16(sa + (uint32_t)(r * PA + c4 * 4) * 4u, src);
        }
        #pragma unroll
        for (int t = 0; t < 4; t++) {
            int id = tid + t * NTHREADS;
            int r  = id >> 3;                  // n row 0..127
            int c4 = id & 7;
            cp16(sb + (uint32_t)(r * PA + c4 * 4) * 4u,
                 B + (size_t)(bn + r) * ldb + kk + c4 * 4);
        }
        cp_commit();
    };

    prefetch(0);
    prefetch(1);

    #pragma unroll 1
    for (int it = 0; it < nit; it++) {
        cp_wait<1>();
        __syncthreads();
        if (it + 2 < nit) prefetch(it + 2);

        const int st = it % STAGES;
        const uint32_t sa = smB + (uint32_t)(st * STAGE_F) * 4u;
        const uint32_t sb = sa + (uint32_t)SBUFA * 4u;

        #pragma unroll
        for (int ks = 0; ks < 4; ks++) {
            const int kc = ks * 8;
            uint32_t af[4][4];
            #pragma unroll
            for (int mt = 0; mt < 4; mt++) {
                int m = warp_m * 64 + mt * 16;
                uint32_t addr = sa + (uint32_t)((m + a_row) * PA + kc + a_col) * 4u;
                ldsm4(af[mt][0], af[mt][1], af[mt][2], af[mt][3], addr);
            }
            uint32_t bf[4][2];
            #pragma unroll
            for (int np = 0; np < 2; np++) {   // each ldsm4 covers 2 nt groups
                int n = warp_n * 32 + np * 16;
                uint32_t addr = sb + (uint32_t)((n + b_row) * PA + kc + b_col) * 4u;
                ldsm4(bf[np*2][0], bf[np*2][1], bf[np*2+1][0], bf[np*2+1][1], addr);
            }
            #pragma unroll
            for (int mt = 0; mt < 4; mt++)
                #pragma unroll
                for (int nt = 0; nt < 4; nt++)
                    mma_tf32(acc[mt][nt], af[mt][0], af[mt][1], af[mt][2], af[mt][3],
                             bf[nt][0], bf[nt][1]);
        }
    }

    // ---- epilogue ----
    #pragma unroll
    for (int mt = 0; mt < 4; mt++) {
        #pragma unroll
        for (int nt = 0; nt < 4; nt++) {
            int r0 = bm + warp_m * 64 + mt * 16 + g;
            int cc = bn + warp_n * 32 + nt * 8 + tg * 2;
            #pragma unroll
            for (int half = 0; half < 2; half++) {
                int r = r0 + half * 8;
                float v0 = acc[mt][nt][half * 2 + 0];
                float v1 = acc[mt][nt][half * 2 + 1];
                size_t gix = (size_t)r * ldc + cc;
                float o0, o1;
                if (EPI == EPI_GATE) {
                    float gt0 = 1.f / (1.f + expf(-(v0 + bias[cc])));
                    float gt1 = 1.f / (1.f + expf(-(v1 + bias[cc + 1])));
                    o0 = gt0 * res0[gix]     + (1.f - gt0) * res1[gix];
                    o1 = gt1 * res0[gix + 1] + (1.f - gt1) * res1[gix + 1];
                } else if (EPI == EPI_SCALE) {
                    o0 = v0 * scale; o1 = v1 * scale;
                } else if (EPI == EPI_ADD) {
                    o0 = v0 + res0[gix]; o1 = v1 + res0[gix + 1];
                } else if (EPI == EPI_GELU) {
                    float x0 = v0 + bias[cc], x1 = v1 + bias[cc + 1];
                    o0 = 0.5f * x0 * (1.f + erff(x0 * 0.70710678118654752440f));
                    o1 = 0.5f * x1 * (1.f + erff(x1 * 0.70710678118654752440f));
                } else { // EPI_BIAS_RES
                    o0 = v0 + bias[cc]     + res0[gix];
                    o1 = v1 + bias[cc + 1] + res0[gix + 1];
                }
                *reinterpret_cast<float2*>(&C[gix]) = make_float2(o0, o1);
            }
        }
    }
}

// ---------------------------------------------------------------------------
// Tiled transpose: out[c][r] = in[r][c].  grid (C/32, R/32, batch), block (32,8)
// ---------------------------------------------------------------------------
__global__ void __launch_bounds__(256)
transpose_kernel(const float* __restrict__ in, float* __restrict__ out,
                 int R, int C)
{
    __shared__ float t[32][33];
    const size_t boff = (size_t)blockIdx.z * R * C;
    in  += boff;
    out += boff;
    int r0 = blockIdx.y * 32, c0 = blockIdx.x * 32;
    int x = threadIdx.x, y = threadIdx.y;
    #pragma unroll
    for (int i = 0; i < 32; i += 8)
        t[y + i][x] = in[(size_t)(r0 + y + i) * C + c0 + x];
    __syncthreads();
    #pragma unroll
    for (int i = 0; i < 32; i += 8)
        out[(size_t)(c0 + y + i) * R + r0 + x] = t[x][y + i];
}

// ---------------------------------------------------------------------------
// Warp helpers
// ---------------------------------------------------------------------------
__device__ __forceinline__ float warpMax(float v) {
    #pragma unroll
    for (int o = 16; o > 0; o >>= 1) v = fmaxf(v, __shfl_xor_sync(0xffffffffu, v, o));
    return v;
}
__device__ __forceinline__ float warpSum(float v) {
    #pragma unroll
    for (int o = 16; o > 0; o >>= 1) v += __shfl_xor_sync(0xffffffffu, v, o);
    return v;
}

// ---------------------------------------------------------------------------
// Row softmax over 2048 cols, in place
// ---------------------------------------------------------------------------
__global__ void __launch_bounds__(256)
softmax_kernel(float* __restrict__ S)
{
    float* p = S + (size_t)blockIdx.x * SEQ;
    const int tid  = threadIdx.x;
    const int lane = tid & 31;
    const int wid  = tid >> 5;
    __shared__ float sh[8];

    float v[8];
    *reinterpret_cast<float4*>(&v[0]) = *reinterpret_cast<const float4*>(&p[tid * 8]);
    *reinterpret_cast<float4*>(&v[4]) = *reinterpret_cast<const float4*>(&p[tid * 8 + 4]);

    float m = v[0];
    #pragma unroll
    for (int i = 1; i < 8; i++) m = fmaxf(m, v[i]);
    m = warpMax(m);
    if (lane == 0) sh[wid] = m;
    __syncthreads();
    m = sh[0];
    #pragma unroll
    for (int w = 1; w < 8; w++) m = fmaxf(m, sh[w]);
    __syncthreads();

    float s = 0.f;
    #pragma unroll
    for (int i = 0; i < 8; i++) { v[i] = expf(v[i] - m); s += v[i]; }
    s = warpSum(s);
    if (lane == 0) sh[wid] = s;
    __syncthreads();
    float tot = sh[0];
    #pragma unroll
    for (int w = 1; w < 8; w++) tot += sh[w];
    float inv = 1.f / tot;

    #pragma unroll
    for (int i = 0; i < 8; i++) v[i] *= inv;
    *reinterpret_cast<float4*>(&p[tid * 8])     = *reinterpret_cast<float4*>(&v[0]);
    *reinterpret_cast<float4*>(&p[tid * 8 + 4]) = *reinterpret_cast<float4*>(&v[4]);
}

// ---------------------------------------------------------------------------
// LayerNorm over last dim (512)
// ---------------------------------------------------------------------------
__global__ void __launch_bounds__(128)
layernorm_kernel(const float* __restrict__ in, float* __restrict__ out,
                 const float* __restrict__ gamma, const float* __restrict__ beta)
{
    const size_t base = (size_t)blockIdx.x * DIM;
    const int tid  = threadIdx.x;
    const int lane = tid & 31;
    const int wid  = tid >> 5;
    __shared__ float shs[4], shq[4];

    float4 x = *reinterpret_cast<const float4*>(&in[base + tid * 4]);
    float s  = x.x + x.y + x.z + x.w;
    float ss = x.x * x.x + x.y * x.y + x.z * x.z + x.w * x.w;
    s  = warpSum(s);
    ss = warpSum(ss);
    if (lane == 0) { shs[wid] = s; shq[wid] = ss; }
    __syncthreads();
    float sum = shs[0] + shs[1] + shs[2] + shs[3];
    float sq  = shq[0] + shq[1] + shq[2] + shq[3];
    float mu  = sum * (1.f / DIM);
    float var = sq * (1.f / DIM) - mu * mu;
    float rs  = rsqrtf(var + 1e-5f);

    float4 gm = *reinterpret_cast<const float4*>(&gamma[tid * 4]);
    float4 bt = *reinterpret_cast<const float4*>(&beta[tid * 4]);
    float4 o;
    o.x = (x.x - mu) * rs * gm.x + bt.x;
    o.y = (x.y - mu) * rs * gm.y + bt.y;
    o.z = (x.z - mu) * rs * gm.z + bt.z;
    o.w = (x.w - mu) * rs * gm.w + bt.w;
    *reinterpret_cast<float4*>(&out[base + tid * 4]) = o;
}

// ---------------------------------------------------------------------------
// Launch
// ---------------------------------------------------------------------------
extern "C" void kernel_launch(void* const* d_in, const int* in_sizes, int n_in,
                              void* d_out, int out_size)
{
    const float* Noise = (const float*)d_in[0];
    const float* X     = (const float*)d_in[1];
    const float* cond  = (const float*)d_in[2];
    const float* Wg    = (const float*)d_in[3];
    const float* bg    = (const float*)d_in[4];
    const float* W1    = (const float*)d_in[5];
    const float* b1    = (const float*)d_in[6];
    const float* W2    = (const float*)d_in[7];
    const float* b2    = (const float*)d_in[8];
    const float* g1    = (const float*)d_in[9];
    const float* be1   = (const float*)d_in[10];
    const float* g2    = (const float*)d_in[11];
    const float* be2   = (const float*)d_in[12];
    float* out = (float*)d_out;

    float *fused, *scores, *q, *h, *y, *xt, *wgt, *w1t, *w2t;
    cudaGetSymbolAddress((void**)&fused,  g_fused);
    cudaGetSymbolAddress((void**)&scores, g_scores);
    cudaGetSymbolAddress((void**)&q,      g_q);
    cudaGetSymbolAddress((void**)&h,      g_h);
    cudaGetSymbolAddress((void**)&y,      g_y);
    cudaGetSymbolAddress((void**)&xt,     g_xt);
    cudaGetSymbolAddress((void**)&wgt,    g_wgt);
    cudaGetSymbolAddress((void**)&w1t,    g_w1t);
    cudaGetSymbolAddress((void**)&w2t,    g_w2t);

    cudaFuncSetAttribute(gemm_mma<EPI_GATE, true>,      cudaFuncAttributeMaxDynamicSharedMemorySize, SMEM_BYTES_G);
    cudaFuncSetAttribute(gemm_mma<EPI_SCALE, false>,    cudaFuncAttributeMaxDynamicSharedMemorySize, SMEM_BYTES_G);
    cudaFuncSetAttribute(gemm_mma<EPI_ADD, false>,      cudaFuncAttributeMaxDynamicSharedMemorySize, SMEM_BYTES_G);
    cudaFuncSetAttribute(gemm_mma<EPI_GELU, false>,     cudaFuncAttributeMaxDynamicSharedMemorySize, SMEM_BYTES_G);
    cudaFuncSetAttribute(gemm_mma<EPI_BIAS_RES, false>, cudaFuncAttributeMaxDynamicSharedMemorySize, SMEM_BYTES_G);

    const float scale = 0.04419417382415922f;  // 1/sqrt(512)

    // 0. transposes: weights -> [N,K]; X -> X^T per batch
    transpose_kernel<<<dim3(DIM / 32, 2 * DIM / 32, 1), dim3(32, 8)>>>(Wg, wgt, 2 * DIM, DIM);
    transpose_kernel<<<dim3(2 * DIM / 32, DIM / 32, 1), dim3(32, 8)>>>(W1, w1t, DIM, 2 * DIM);
    transpose_kernel<<<dim3(DIM / 32, 2 * DIM / 32, 1), dim3(32, 8)>>>(W2, w2t, 2 * DIM, DIM);
    transpose_kernel<<<dim3(DIM / 32, SEQ / 32, BATCH), dim3(32, 8)>>>(X, xt, SEQ, DIM);

    // 1. gate = sigmoid(concat(Noise,cond) @ Wg + bg); fused = gate*Noise + (1-gate)*cond
    gemm_mma<EPI_GATE, true><<<dim3(DIM / BN, NTOK / BM, 1), NTHREADS, SMEM_BYTES_G>>>(
        Noise, cond, wgt, fused,
        2 * DIM, 2 * DIM, 2 * DIM, DIM,
        0, 0, 0, bg, Noise, cond, 0.f);

    // 2. scores = fused @ X^T * scale  (batched, B = X [S,D] already K-contig)
    gemm_mma<EPI_SCALE, false><<<dim3(SEQ / BN, SEQ / BM, BATCH), NTHREADS, SMEM_BYTES_G>>>(
        fused, nullptr, X, scores,
        DIM, DIM, DIM, SEQ,
        (size_t)SEQ * DIM, (size_t)SEQ * DIM, (size_t)SEQ * SEQ,
        nullptr, nullptr, nullptr, scale);

    // 3. softmax (in place)
    softmax_kernel<<<NTOK, 256>>>(scores);

    // 4. fused += attn @ X  (batched, B = X^T [D,S] K-contig)
    gemm_mma<EPI_ADD, false><<<dim3(DIM / BN, SEQ / BM, BATCH), NTHREADS, SMEM_BYTES_G>>>(
        scores, nullptr, xt, fused,
        SEQ, SEQ, SEQ, DIM,
        (size_t)SEQ * SEQ, (size_t)DIM * SEQ, (size_t)SEQ * DIM,
        nullptr, fused, nullptr, 0.f);

    // 5. q = LN1(fused)
    layernorm_kernel<<<NTOK, 128>>>(fused, q, g1, be1);

    // 6. h = gelu(q @ W1 + b1)   (B = W1^T [2D, D])
    gemm_mma<EPI_GELU, false><<<dim3(2 * DIM / BN, NTOK / BM, 1), NTHREADS, SMEM_BYTES_G>>>(
        q, nullptr, w1t, h,
        DIM, DIM, DIM, 2 * DIM,
        0, 0, 0, b1, nullptr, nullptr, 0.f);

    // 7. y = h @ W2 + b2 + q     (B = W2^T [D, 2D])
    gemm_mma<EPI_BIAS_RES, false><<<dim3(DIM / BN, NTOK / BM, 1), NTHREADS, SMEM_BYTES_G>>>(
        h, nullptr, w2t, y,
        2 * DIM, 2 * DIM, 2 * DIM, DIM,
        0, 0, 0, b2, q, nullptr, 0.f);

    // 8. out = LN2(y)
    layernorm_kernel<<<NTOK, 128>>>(y, out, g2, be2);
}

// round 10
// speedup vs baseline: 1.5251x; 1.4234x over previous
#include <cuda_runtime.h>
#include <cuda_fp16.h>
#include <math.h>
#include <stdint.h>

// ---------------------------------------------------------------------------
// Problem constants
// ---------------------------------------------------------------------------
#define BATCH   8
#define SEQ     2048
#define DIM     512
#define NTOK    (BATCH * SEQ)          // 16384

// GEMM tiling (mma.sync m16n8k16 fp16)
#define BM 128
#define BN 128
#define BK 32                          // fp16 elements of K per stage
#define NTHREADS 256                   // 8 warps, 2x4, 64x32 warp tiles
#define STAGES 3

// smem pitch in fp16 elements: 32 k + 8 pad = 40 (80 B rows; ldmatrix conflict-free)
#define PA 40
#define SBUFA (128 * PA)               // fp16 elements
#define SBUFB (128 * PA)
#define STAGE_H (SBUFA + SBUFB)
#define SMEM_BYTES_G (STAGES * STAGE_H * 2)   // 61440 B -> 2 CTAs/SM easily

// Epilogue tags
#define EPI_GATE     0
#define EPI_SCALE    1
#define EPI_ADD      2
#define EPI_GELU     3
#define EPI_BIAS_RES 4

// ---------------------------------------------------------------------------
// Scratch (device globals: allocation-free rule)
// ---------------------------------------------------------------------------
__device__ float  g_fused  [(size_t)NTOK * DIM];
__device__ float  g_scores [(size_t)BATCH * SEQ * SEQ];
__device__ float  g_q      [(size_t)NTOK * DIM];
__device__ float  g_y      [(size_t)NTOK * DIM];
__device__ __half g_fusedh [(size_t)NTOK * DIM];
__device__ __half g_attnh  [(size_t)BATCH * SEQ * SEQ];
__device__ __half g_qh     [(size_t)NTOK * DIM];
__device__ __half g_hh     [(size_t)NTOK * 2 * DIM];
__device__ __half g_noiseh [(size_t)NTOK * DIM];
__device__ __half g_condh  [(size_t)NTOK * DIM];
__device__ __half g_xh     [(size_t)NTOK * DIM];        // X fp16 [S,D] per batch
__device__ __half g_xth    [(size_t)BATCH * DIM * SEQ]; // X^T fp16 [D,S]
__device__ __half g_wgth   [(size_t)DIM * 2 * DIM];     // Wg^T [D, 2D]
__device__ __half g_w1th   [(size_t)2 * DIM * DIM];     // W1^T [2D, D]
__device__ __half g_w2th   [(size_t)DIM * 2 * DIM];     // W2^T [D, 2D]

// ---------------------------------------------------------------------------
// PTX helpers
// ---------------------------------------------------------------------------
__device__ __forceinline__ uint32_t smem_u32(const void* p) {
    uint32_t a;
    asm("{ .reg .u64 t; cvta.to.shared.u64 t, %1; cvt.u32.u64 %0, t; }" : "=r"(a) : "l"(p));
    return a;
}
__device__ __forceinline__ void cp16(uint32_t saddr, const void* gaddr) {
    asm volatile("cp.async.cg.shared.global [%0], [%1], 16;" :: "r"(saddr), "l"(gaddr));
}
__device__ __forceinline__ void cp_commit() {
    asm volatile("cp.async.commit_group;" ::: "memory");
}
template<int N>
__device__ __forceinline__ void cp_wait() {
    asm volatile("cp.async.wait_group %0;" :: "n"(N) : "memory");
}
__device__ __forceinline__ void mma_f16(float* c, uint32_t a0, uint32_t a1,
                                        uint32_t a2, uint32_t a3,
                                        uint32_t b0, uint32_t b1) {
    asm volatile("mma.sync.aligned.m16n8k16.row.col.f32.f16.f16.f32 "
                 "{%0,%1,%2,%3}, {%4,%5,%6,%7}, {%8,%9}, {%0,%1,%2,%3};"
                 : "+f"(c[0]), "+f"(c[1]), "+f"(c[2]), "+f"(c[3])
                 : "r"(a0), "r"(a1), "r"(a2), "r"(a3), "r"(b0), "r"(b1));
}
__device__ __forceinline__ void ldsm4(uint32_t& r0, uint32_t& r1, uint32_t& r2,
                                      uint32_t& r3, uint32_t addr) {
    asm volatile("ldmatrix.sync.aligned.m8n8.x4.shared.b16 {%0,%1,%2,%3}, [%4];"
                 : "=r"(r0), "=r"(r1), "=r"(r2), "=r"(r3) : "r"(addr));
}

// ---------------------------------------------------------------------------
// fp16 tensor-core GEMM: C[M,N] = A[M,K] * B^T, A [M,K], B [N,K] (K-contig).
// 128x128x32 CTA tile, 8 warps (2x4), 64x32 warp tiles, ldmatrix fragments,
// 3-stage cp.async ring, 1 barrier per K-iter.  fp32 accumulate.
// SPLITA: A cols [0,512) from A, [512,1024) from A2 (virtual concat).
// Writes C (fp32) unless EPI_GELU (writes only Ch fp16); EPI_GATE writes both.
// ---------------------------------------------------------------------------
template<int EPI, bool SPLITA>
__global__ void __launch_bounds__(NTHREADS, 2)
gemm_mma(const __half* __restrict__ A, const __half* __restrict__ A2,
         const __half* __restrict__ B,
         float* __restrict__ C, __half* __restrict__ Ch,
         int K, int lda, int ldb, int ldc,
         size_t strA, size_t strB, size_t strC,
         const float* __restrict__ bias,
         const float* __restrict__ res0,
         const float* __restrict__ res1,
         float scale)
{
    extern __shared__ __half hsm[];

    const int z = blockIdx.z;
    A += (size_t)z * strA;
    B += (size_t)z * strB;
    if (C)  C  += (size_t)z * strC;
    if (Ch) Ch += (size_t)z * strC;
    if (res0) res0 += (size_t)z * strC;
    if (res1) res1 += (size_t)z * strC;

    const int bm   = blockIdx.y * BM;
    const int bn   = blockIdx.x * BN;
    const int tid  = threadIdx.x;
    const int wid  = tid >> 5;
    const int lane = tid & 31;
    const int warp_m = wid & 1;        // 0..1 -> 64 rows
    const int warp_n = wid >> 1;       // 0..3 -> 32 cols
    const int g  = lane >> 2;          // 0..7
    const int tg = lane & 3;           // 0..3
    const int quad  = lane >> 3;       // 0..3
    const int rowin = lane & 7;        // 0..7

    // ldmatrix per-lane offsets (fp16 units)
    const int a_row = (quad & 1) * 8 + rowin;   // m within 16
    const int a_col = (quad >> 1) * 8;          // k: 0 or 8
    const int b_row = (quad >> 1) * 8 + rowin;  // n within 16
    const int b_col = (quad & 1) * 8;           // k: 0 or 8

    const uint32_t smB = smem_u32(hsm);

    float acc[4][4][4];
    #pragma unroll
    for (int i = 0; i < 4; i++)
        #pragma unroll
        for (int j = 0; j < 4; j++)
            #pragma unroll
            for (int e = 0; e < 4; e++) acc[i][j][e] = 0.f;

    const int nit = K / BK;

    // ---- prefetch one K=32 tile (A 128x32, B 128x32 fp16) ----
    auto prefetch = [&](int it) {
        const int kk = it * BK;
        const int st = it % STAGES;
        const uint32_t sa = smB + (uint32_t)(st * STAGE_H) * 2u;
        const uint32_t sb = sa + (uint32_t)SBUFA * 2u;
        // 128 rows x 4 chunks (8 fp16 each) = 512 chunks -> 2 per thread
        #pragma unroll
        for (int t = 0; t < 2; t++) {
            int id = tid + t * NTHREADS;       // 0..511
            int r  = id >> 2;                  // 0..127
            int c8 = id & 3;                   // chunk of 8 fp16
            int col = kk + c8 * 8;
            const __half* src;
            if (SPLITA) {
                src = (col < DIM) ? (A  + (size_t)(bm + r) * DIM + col)
                                  : (A2 + (size_t)(bm + r) * DIM + (col - DIM));
            } else {
                src = A + (size_t)(bm + r) * lda + col;
            }
            cp16(sa + (uint32_t)(r * PA + c8 * 8) * 2u, src);
        }
        #pragma unroll
        for (int t = 0; t < 2; t++) {
            int id = tid + t * NTHREADS;
            int r  = id >> 2;
            int c8 = id & 3;
            cp16(sb + (uint32_t)(r * PA + c8 * 8) * 2u,
                 B + (size_t)(bn + r) * ldb + kk + c8 * 8);
        }
        cp_commit();
    };

    prefetch(0);
    prefetch(1);

    #pragma unroll 1
    for (int it = 0; it < nit; it++) {
        cp_wait<1>();
        __syncthreads();
        if (it + 2 < nit) prefetch(it + 2);

        const int st = it % STAGES;
        const uint32_t sa = smB + (uint32_t)(st * STAGE_H) * 2u;
        const uint32_t sb = sa + (uint32_t)SBUFA * 2u;

        #pragma unroll
        for (int ks = 0; ks < 2; ks++) {       // 2 x k16 per BK=32
            const int kc = ks * 16;
            uint32_t af[4][4];
            #pragma unroll
            for (int mt = 0; mt < 4; mt++) {
                int m = warp_m * 64 + mt * 16;
                uint32_t addr = sa + (uint32_t)((m + a_row) * PA + kc + a_col) * 2u;
                ldsm4(af[mt][0], af[mt][1], af[mt][2], af[mt][3], addr);
            }
            uint32_t bf[4][2];
            #pragma unroll
            for (int np = 0; np < 2; np++) {   // each ldsm4 covers n16 (2 n8 groups)
                int n = warp_n * 32 + np * 16;
                uint32_t addr = sb + (uint32_t)((n + b_row) * PA + kc + b_col) * 2u;
                ldsm4(bf[np*2][0], bf[np*2][1], bf[np*2+1][0], bf[np*2+1][1], addr);
            }
            #pragma unroll
            for (int mt = 0; mt < 4; mt++)
                #pragma unroll
                for (int nt = 0; nt < 4; nt++)
                    mma_f16(acc[mt][nt], af[mt][0], af[mt][1], af[mt][2], af[mt][3],
                            bf[nt][0], bf[nt][1]);
        }
    }

    // ---- epilogue ----
    #pragma unroll
    for (int mt = 0; mt < 4; mt++) {
        #pragma unroll
        for (int nt = 0; nt < 4; nt++) {
            int r0 = bm + warp_m * 64 + mt * 16 + g;
            int cc = bn + warp_n * 32 + nt * 8 + tg * 2;
            #pragma unroll
            for (int half = 0; half < 2; half++) {
                int r = r0 + half * 8;
                float v0 = acc[mt][nt][half * 2 + 0];
                float v1 = acc[mt][nt][half * 2 + 1];
                size_t gix = (size_t)r * ldc + cc;
                float o0, o1;
                if (EPI == EPI_GATE) {
                    float gt0 = 1.f / (1.f + expf(-(v0 + bias[cc])));
                    float gt1 = 1.f / (1.f + expf(-(v1 + bias[cc + 1])));
                    o0 = gt0 * res0[gix]     + (1.f - gt0) * res1[gix];
                    o1 = gt1 * res0[gix + 1] + (1.f - gt1) * res1[gix + 1];
                } else if (EPI == EPI_SCALE) {
                    o0 = v0 * scale; o1 = v1 * scale;
                } else if (EPI == EPI_ADD) {
                    o0 = v0 + res0[gix]; o1 = v1 + res0[gix + 1];
                } else if (EPI == EPI_GELU) {
                    float x0 = v0 + bias[cc], x1 = v1 + bias[cc + 1];
                    o0 = 0.5f * x0 * (1.f + erff(x0 * 0.70710678118654752440f));
                    o1 = 0.5f * x1 * (1.f + erff(x1 * 0.70710678118654752440f));
                } else { // EPI_BIAS_RES
                    o0 = v0 + bias[cc]     + res0[gix];
                    o1 = v1 + bias[cc + 1] + res0[gix + 1];
                }
                if (EPI != EPI_GELU)
                    *reinterpret_cast<float2*>(&C[gix]) = make_float2(o0, o1);
                if (EPI == EPI_GELU || EPI == EPI_GATE)
                    *reinterpret_cast<__half2*>(&Ch[gix]) = __floats2half2_rn(o0, o1);
            }
        }
    }
}

// ---------------------------------------------------------------------------
// fp32 -> fp16 elementwise convert (vectorized, 4 per thread)
// ---------------------------------------------------------------------------
__global__ void __launch_bounds__(256)
convert_h(const float* __restrict__ in, __half* __restrict__ out)
{
    size_t i4 = (size_t)blockIdx.x * 256 + threadIdx.x;
    float4 v = reinterpret_cast<const float4*>(in)[i4];
    __half2 h0 = __floats2half2_rn(v.x, v.y);
    __half2 h1 = __floats2half2_rn(v.z, v.w);
    reinterpret_cast<__half2*>(out)[i4 * 2]     = h0;
    reinterpret_cast<__half2*>(out)[i4 * 2 + 1] = h1;
}

// ---------------------------------------------------------------------------
// Tiled transpose + convert: out[c][r] = (half) in[r][c]
// grid (C/32, R/32, batch), block (32,8)
// ---------------------------------------------------------------------------
__global__ void __launch_bounds__(256)
transpose_h(const float* __restrict__ in, __half* __restrict__ out,
            int R, int C)
{
    __shared__ float t[32][33];
    in  += (size_t)blockIdx.z * R * C;
    out += (size_t)blockIdx.z * R * C;
    int r0 = blockIdx.y * 32, c0 = blockIdx.x * 32;
    int x = threadIdx.x, y = threadIdx.y;
    #pragma unroll
    for (int i = 0; i < 32; i += 8)
        t[y + i][x] = in[(size_t)(r0 + y + i) * C + c0 + x];
    __syncthreads();
    #pragma unroll
    for (int i = 0; i < 32; i += 8)
        out[(size_t)(c0 + y + i) * R + r0 + x] = __float2half_rn(t[x][y + i]);
}

// ---------------------------------------------------------------------------
// Warp helpers
// ---------------------------------------------------------------------------
__device__ __forceinline__ float warpMax(float v) {
    #pragma unroll
    for (int o = 16; o > 0; o >>= 1) v = fmaxf(v, __shfl_xor_sync(0xffffffffu, v, o));
    return v;
}
__device__ __forceinline__ float warpSum(float v) {
    #pragma unroll
    for (int o = 16; o > 0; o >>= 1) v += __shfl_xor_sync(0xffffffffu, v, o);
    return v;
}

// ---------------------------------------------------------------------------
// Row softmax over 2048 fp32 logits -> fp16 weights
// ---------------------------------------------------------------------------
__global__ void __launch_bounds__(256)
softmax_kernel(const float* __restrict__ S, __half* __restrict__ O)
{
    const float* p = S + (size_t)blockIdx.x * SEQ;
    __half* o = O + (size_t)blockIdx.x * SEQ;
    const int tid  = threadIdx.x;
    const int lane = tid & 31;
    const int wid  = tid >> 5;
    __shared__ float sh[8];

    float v[8];
    *reinterpret_cast<float4*>(&v[0]) = *reinterpret_cast<const float4*>(&p[tid * 8]);
    *reinterpret_cast<float4*>(&v[4]) = *reinterpret_cast<const float4*>(&p[tid * 8 + 4]);

    float m = v[0];
    #pragma unroll
    for (int i = 1; i < 8; i++) m = fmaxf(m, v[i]);
    m = warpMax(m);
    if (lane == 0) sh[wid] = m;
    __syncthreads();
    m = sh[0];
    #pragma unroll
    for (int w = 1; w < 8; w++) m = fmaxf(m, sh[w]);
    __syncthreads();

    float s = 0.f;
    #pragma unroll
    for (int i = 0; i < 8; i++) { v[i] = expf(v[i] - m); s += v[i]; }
    s = warpSum(s);
    if (lane == 0) sh[wid] = s;
    __syncthreads();
    float tot = sh[0];
    #pragma unroll
    for (int w = 1; w < 8; w++) tot += sh[w];
    float inv = 1.f / tot;

    __half2 hv[4];
    #pragma unroll
    for (int i = 0; i < 4; i++)
        hv[i] = __floats2half2_rn(v[i*2] * inv, v[i*2+1] * inv);
    *reinterpret_cast<__half2*>(&o[tid * 8])     = hv[0];
    *reinterpret_cast<__half2*>(&o[tid * 8 + 2]) = hv[1];
    *reinterpret_cast<__half2*>(&o[tid * 8 + 4]) = hv[2];
    *reinterpret_cast<__half2*>(&o[tid * 8 + 6]) = hv[3];
}

// ---------------------------------------------------------------------------
// LayerNorm over last dim (512); optional fp16 companion output
// ---------------------------------------------------------------------------
__global__ void __launch_bounds__(128)
layernorm_kernel(const float* __restrict__ in, float* __restrict__ out,
                 __half* __restrict__ out_h,
                 const float* __restrict__ gamma, const float* __restrict__ beta)
{
    const size_t base = (size_t)blockIdx.x * DIM;
    const int tid  = threadIdx.x;
    const int lane = tid & 31;
    const int wid  = tid >> 5;
    __shared__ float shs[4], shq[4];

    float4 x = *reinterpret_cast<const float4*>(&in[base + tid * 4]);
    float s  = x.x + x.y + x.z + x.w;
    float ss = x.x * x.x + x.y * x.y + x.z * x.z + x.w * x.w;
    s  = warpSum(s);
    ss = warpSum(ss);
    if (lane == 0) { shs[wid] = s; shq[wid] = ss; }
    __syncthreads();
    float sum = shs[0] + shs[1] + shs[2] + shs[3];
    float sq  = shq[0] + shq[1] + shq[2] + shq[3];
    float mu  = sum * (1.f / DIM);
    float var = sq * (1.f / DIM) - mu * mu;
    float rs  = rsqrtf(var + 1e-5f);

    float4 gm = *reinterpret_cast<const float4*>(&gamma[tid * 4]);
    float4 bt = *reinterpret_cast<const float4*>(&beta[tid * 4]);
    float4 o;
    o.x = (x.x - mu) * rs * gm.x + bt.x;
    o.y = (x.y - mu) * rs * gm.y + bt.y;
    o.z = (x.z - mu) * rs * gm.z + bt.z;
    o.w = (x.w - mu) * rs * gm.w + bt.w;
    *reinterpret_cast<float4*>(&out[base + tid * 4]) = o;
    if (out_h) {
        *reinterpret_cast<__half2*>(&out_h[base + tid * 4])     = __floats2half2_rn(o.x, o.y);
        *reinterpret_cast<__half2*>(&out_h[base + tid * 4 + 2]) = __floats2half2_rn(o.z, o.w);
    }
}

// ---------------------------------------------------------------------------
// Launch
// ---------------------------------------------------------------------------
extern "C" void kernel_launch(void* const* d_in, const int* in_sizes, int n_in,
                              void* d_out, int out_size)
{
    const float* Noise = (const float*)d_in[0];
    const float* X     = (const float*)d_in[1];
    const float* cond  = (const float*)d_in[2];
    const float* Wg    = (const float*)d_in[3];
    const float* bg    = (const float*)d_in[4];
    const float* W1    = (const float*)d_in[5];
    const float* b1    = (const float*)d_in[6];
    const float* W2    = (const float*)d_in[7];
    const float* b2    = (const float*)d_in[8];
    const float* g1    = (const float*)d_in[9];
    const float* be1   = (const float*)d_in[10];
    const float* g2    = (const float*)d_in[11];
    const float* be2   = (const float*)d_in[12];
    float* out = (float*)d_out;

    float *fused, *scores, *q, *y;
    __half *fusedh, *attnh, *qh, *hh, *noiseh, *condh, *xh, *xth, *wgth, *w1th, *w2th;
    cudaGetSymbolAddress((void**)&fused,  g_fused);
    cudaGetSymbolAddress((void**)&scores, g_scores);
    cudaGetSymbolAddress((void**)&q,      g_q);
    cudaGetSymbolAddress((void**)&y,      g_y);
    cudaGetSymbolAddress((void**)&fusedh, g_fusedh);
    cudaGetSymbolAddress((void**)&attnh,  g_attnh);
    cudaGetSymbolAddress((void**)&qh,     g_qh);
    cudaGetSymbolAddress((void**)&hh,     g_hh);
    cudaGetSymbolAddress((void**)&noiseh, g_noiseh);
    cudaGetSymbolAddress((void**)&condh,  g_condh);
    cudaGetSymbolAddress((void**)&xh,     g_xh);
    cudaGetSymbolAddress((void**)&xth,    g_xth);
    cudaGetSymbolAddress((void**)&wgth,   g_wgth);
    cudaGetSymbolAddress((void**)&w1th,   g_w1th);
    cudaGetSymbolAddress((void**)&w2th,   g_w2th);

    cudaFuncSetAttribute(gemm_mma<EPI_GATE, true>,      cudaFuncAttributeMaxDynamicSharedMemorySize, SMEM_BYTES_G);
    cudaFuncSetAttribute(gemm_mma<EPI_SCALE, false>,    cudaFuncAttributeMaxDynamicSharedMemorySize, SMEM_BYTES_G);
    cudaFuncSetAttribute(gemm_mma<EPI_ADD, false>,      cudaFuncAttributeMaxDynamicSharedMemorySize, SMEM_BYTES_G);
    cudaFuncSetAttribute(gemm_mma<EPI_GELU, false>,     cudaFuncAttributeMaxDynamicSharedMemorySize, SMEM_BYTES_G);
    cudaFuncSetAttribute(gemm_mma<EPI_BIAS_RES, false>, cudaFuncAttributeMaxDynamicSharedMemorySize, SMEM_BYTES_G);

    const float scale = 0.04419417382415922f;  // 1/sqrt(512)
    const int NEL = NTOK * DIM;                // 8,388,608

    // 0a. elementwise fp16 conversions
    convert_h<<<NEL / 4 / 256, 256>>>(Noise, noiseh);
    convert_h<<<NEL / 4 / 256, 256>>>(cond,  condh);
    convert_h<<<NEL / 4 / 256, 256>>>(X,     xh);
    // 0b. transpose + convert: weights -> [N,K] fp16; X -> X^T fp16
    transpose_h<<<dim3(DIM / 32, 2 * DIM / 32, 1), dim3(32, 8)>>>(Wg, wgth, 2 * DIM, DIM);
    transpose_h<<<dim3(2 * DIM / 32, DIM / 32, 1), dim3(32, 8)>>>(W1, w1th, DIM, 2 * DIM);
    transpose_h<<<dim3(DIM / 32, 2 * DIM / 32, 1), dim3(32, 8)>>>(W2, w2th, 2 * DIM, DIM);
    transpose_h<<<dim3(DIM / 32, SEQ / 32, BATCH), dim3(32, 8)>>>(X, xth, SEQ, DIM);

    // 1. gate = sigmoid(concat(Noise,cond) @ Wg + bg); fused = gate*Noise+(1-gate)*cond
    gemm_mma<EPI_GATE, true><<<dim3(DIM / BN, NTOK / BM, 1), NTHREADS, SMEM_BYTES_G>>>(
        noiseh, condh, wgth, fused, fusedh,
        2 * DIM, 2 * DIM, 2 * DIM, DIM,
        0, 0, 0, bg, Noise, cond, 0.f);

    // 2. scores = fused @ X^T * scale  (batched; B = X fp16 [S,D] K-contig)
    gemm_mma<EPI_SCALE, false><<<dim3(SEQ / BN, SEQ / BM, BATCH), NTHREADS, SMEM_BYTES_G>>>(
        fusedh, nullptr, xh, scores, nullptr,
        DIM, DIM, DIM, SEQ,
        (size_t)SEQ * DIM, (size_t)SEQ * DIM, (size_t)SEQ * SEQ,
        nullptr, nullptr, nullptr, scale);

    // 3. softmax: fp32 logits -> fp16 weights
    softmax_kernel<<<NTOK, 256>>>(scores, attnh);

    // 4. fused += attn @ X  (batched; A = attn fp16, B = X^T fp16 [D,S])
    gemm_mma<EPI_ADD, false><<<dim3(DIM / BN, SEQ / BM, BATCH), NTHREADS, SMEM_BYTES_G>>>(
        attnh, nullptr, xth, fused, nullptr,
        SEQ, SEQ, SEQ, DIM,
        (size_t)SEQ * SEQ, (size_t)DIM * SEQ, (size_t)SEQ * DIM,
        nullptr, fused, nullptr, 0.f);

    // 5. q = LN1(fused)  (+ fp16 companion)
    layernorm_kernel<<<NTOK, 128>>>(fused, q, qh, g1, be1);

    // 6. h = gelu(q @ W1 + b1)  -> fp16 only
    gemm_mma<EPI_GELU, false><<<dim3(2 * DIM / BN, NTOK / BM, 1), NTHREADS, SMEM_BYTES_G>>>(
        qh, nullptr, w1th, nullptr, hh,
        DIM, DIM, DIM, 2 * DIM,
        0, 0, 0, b1, nullptr, nullptr, 0.f);

    // 7. y = h @ W2 + b2 + q
    gemm_mma<EPI_BIAS_RES, false><<<dim3(DIM / BN, NTOK / BM, 1), NTHREADS, SMEM_BYTES_G>>>(
        hh, nullptr, w2th, y, nullptr,
        2 * DIM, 2 * DIM, 2 * DIM, DIM,
        0, 0, 0, b2, q, nullptr, 0.f);

    // 8. out = LN2(y)
    layernorm_kernel<<<NTOK, 128>>>(y, out, nullptr, g2, be2);
}

// round 11
// speedup vs baseline: 1.6734x; 1.0972x over previous
#include <cuda_runtime.h>
#include <cuda_fp16.h>
#include <math.h>
#include <stdint.h>

// ---------------------------------------------------------------------------
// Problem constants
// ---------------------------------------------------------------------------
#define BATCH   8
#define SEQ     2048
#define DIM     512
#define NTOK    (BATCH * SEQ)          // 16384

// GEMM tiling (mma.sync m16n8k16 fp16)
#define BM 128
#define BN 128
#define BK 64                          // fp16 elements of K per stage
#define NTHREADS 256                   // 8 warps, 2x4, 64x32 warp tiles
#define STAGES 3

// smem pitch in fp16 elements: 64 k + 8 pad = 72 (144 B rows; ldmatrix conflict-free)
#define PA 72
#define SBUFA (128 * PA)               // fp16 elements
#define SBUFB (128 * PA)
#define STAGE_H (SBUFA + SBUFB)
#define SMEM_BYTES_G (STAGES * STAGE_H * 2)   // 110592 B -> 2 CTAs/SM

// Epilogue tags
#define EPI_GATE     0
#define EPI_SCALE    1
#define EPI_ADD      2
#define EPI_GELU     3
#define EPI_BIAS_RES 4

// ---------------------------------------------------------------------------
// Scratch (device globals: allocation-free rule)
// ---------------------------------------------------------------------------
__device__ float  g_fused  [(size_t)NTOK * DIM];
__device__ float  g_q      [(size_t)NTOK * DIM];
__device__ float  g_y      [(size_t)NTOK * DIM];
__device__ __half g_fusedh [(size_t)NTOK * DIM];
__device__ __half g_attnh  [(size_t)BATCH * SEQ * SEQ];  // logits then weights
__device__ __half g_qh     [(size_t)NTOK * DIM];
__device__ __half g_hh     [(size_t)NTOK * 2 * DIM];
__device__ __half g_noiseh [(size_t)NTOK * DIM];
__device__ __half g_condh  [(size_t)NTOK * DIM];
__device__ __half g_xh     [(size_t)NTOK * DIM];         // X fp16 [S,D]
__device__ __half g_xth    [(size_t)BATCH * DIM * SEQ];  // X^T fp16 [D,S]
__device__ __half g_wgth   [(size_t)DIM * 2 * DIM];
__device__ __half g_w1th   [(size_t)2 * DIM * DIM];
__device__ __half g_w2th   [(size_t)DIM * 2 * DIM];

// ---------------------------------------------------------------------------
// PTX helpers
// ---------------------------------------------------------------------------
__device__ __forceinline__ uint32_t smem_u32(const void* p) {
    uint32_t a;
    asm("{ .reg .u64 t; cvta.to.shared.u64 t, %1; cvt.u32.u64 %0, t; }" : "=r"(a) : "l"(p));
    return a;
}
__device__ __forceinline__ void cp16(uint32_t saddr, const void* gaddr) {
    asm volatile("cp.async.cg.shared.global [%0], [%1], 16;" :: "r"(saddr), "l"(gaddr));
}
__device__ __forceinline__ void cp_commit() {
    asm volatile("cp.async.commit_group;" ::: "memory");
}
template<int N>
__device__ __forceinline__ void cp_wait() {
    asm volatile("cp.async.wait_group %0;" :: "n"(N) : "memory");
}
__device__ __forceinline__ void mma_f16(float* c, uint32_t a0, uint32_t a1,
                                        uint32_t a2, uint32_t a3,
                                        uint32_t b0, uint32_t b1) {
    asm volatile("mma.sync.aligned.m16n8k16.row.col.f32.f16.f16.f32 "
                 "{%0,%1,%2,%3}, {%4,%5,%6,%7}, {%8,%9}, {%0,%1,%2,%3};"
                 : "+f"(c[0]), "+f"(c[1]), "+f"(c[2]), "+f"(c[3])
                 : "r"(a0), "r"(a1), "r"(a2), "r"(a3), "r"(b0), "r"(b1));
}
__device__ __forceinline__ void ldsm4(uint32_t& r0, uint32_t& r1, uint32_t& r2,
                                      uint32_t& r3, uint32_t addr) {
    asm volatile("ldmatrix.sync.aligned.m8n8.x4.shared.b16 {%0,%1,%2,%3}, [%4];"
                 : "=r"(r0), "=r"(r1), "=r"(r2), "=r"(r3) : "r"(addr));
}

// ---------------------------------------------------------------------------
// fp16 tensor-core GEMM: C[M,N] = A[M,K] * B^T, A [M,K], B [N,K] (K-contig).
// 128x128x64 CTA tile, 8 warps (2x4), 64x32 warp tiles, ldmatrix fragments,
// 3-stage cp.async ring, 1 barrier per K=64 iter.  fp32 accumulate.
// SPLITA: A cols [0,512) from A, [512,1024) from A2 (virtual concat).
// Output: EPI_GATE -> C + Ch; EPI_SCALE, EPI_GELU -> Ch only; else -> C.
// ---------------------------------------------------------------------------
template<int EPI, bool SPLITA>
__global__ void __launch_bounds__(NTHREADS, 2)
gemm_mma(const __half* __restrict__ A, const __half* __restrict__ A2,
         const __half* __restrict__ B,
         float* __restrict__ C, __half* __restrict__ Ch,
         int K, int lda, int ldb, int ldc,
         size_t strA, size_t strB, size_t strC,
         const float* __restrict__ bias,
         const float* __restrict__ res0,
         const float* __restrict__ res1,
         float scale)
{
    extern __shared__ __half hsm[];

    const int z = blockIdx.z;
    A += (size_t)z * strA;
    B += (size_t)z * strB;
    if (C)  C  += (size_t)z * strC;
    if (Ch) Ch += (size_t)z * strC;
    if (res0) res0 += (size_t)z * strC;
    if (res1) res1 += (size_t)z * strC;

    const int bm   = blockIdx.y * BM;
    const int bn   = blockIdx.x * BN;
    const int tid  = threadIdx.x;
    const int wid  = tid >> 5;
    const int lane = tid & 31;
    const int warp_m = wid & 1;        // 0..1 -> 64 rows
    const int warp_n = wid >> 1;       // 0..3 -> 32 cols
    const int g  = lane >> 2;          // 0..7
    const int tg = lane & 3;           // 0..3
    const int quad  = lane >> 3;       // 0..3
    const int rowin = lane & 7;        // 0..7

    const int a_row = (quad & 1) * 8 + rowin;
    const int a_col = (quad >> 1) * 8;
    const int b_row = (quad >> 1) * 8 + rowin;
    const int b_col = (quad & 1) * 8;

    const uint32_t smB = smem_u32(hsm);

    float acc[4][4][4];
    #pragma unroll
    for (int i = 0; i < 4; i++)
        #pragma unroll
        for (int j = 0; j < 4; j++)
            #pragma unroll
            for (int e = 0; e < 4; e++) acc[i][j][e] = 0.f;

    const int nit = K / BK;

    // ---- prefetch one K=64 tile (A 128x64, B 128x64 fp16) ----
    auto prefetch = [&](int it) {
        const int kk = it * BK;
        const int st = it % STAGES;
        const uint32_t sa = smB + (uint32_t)(st * STAGE_H) * 2u;
        const uint32_t sb = sa + (uint32_t)SBUFA * 2u;
        // 128 rows x 8 chunks (8 fp16 each) = 1024 chunks -> 4 per thread
        #pragma unroll
        for (int t = 0; t < 4; t++) {
            int id = tid + t * NTHREADS;       // 0..1023
            int r  = id >> 3;                  // 0..127
            int c8 = id & 7;                   // chunk of 8 fp16
            int col = kk + c8 * 8;
            const __half* src;
            if (SPLITA) {
                src = (col < DIM) ? (A  + (size_t)(bm + r) * DIM + col)
                                  : (A2 + (size_t)(bm + r) * DIM + (col - DIM));
            } else {
                src = A + (size_t)(bm + r) * lda + col;
            }
            cp16(sa + (uint32_t)(r * PA + c8 * 8) * 2u, src);
        }
        #pragma unroll
        for (int t = 0; t < 4; t++) {
            int id = tid + t * NTHREADS;
            int r  = id >> 3;
            int c8 = id & 7;
            cp16(sb + (uint32_t)(r * PA + c8 * 8) * 2u,
                 B + (size_t)(bn + r) * ldb + kk + c8 * 8);
        }
        cp_commit();
    };

    prefetch(0);
    prefetch(1);

    #pragma unroll 1
    for (int it = 0; it < nit; it++) {
        cp_wait<1>();
        __syncthreads();
        if (it + 2 < nit) prefetch(it + 2);

        const int st = it % STAGES;
        const uint32_t sa = smB + (uint32_t)(st * STAGE_H) * 2u;
        const uint32_t sb = sa + (uint32_t)SBUFA * 2u;

        #pragma unroll
        for (int ks = 0; ks < 4; ks++) {       // 4 x k16 per BK=64
            const int kc = ks * 16;
            uint32_t af[4][4];
            #pragma unroll
            for (int mt = 0; mt < 4; mt++) {
                int m = warp_m * 64 + mt * 16;
                uint32_t addr = sa + (uint32_t)((m + a_row) * PA + kc + a_col) * 2u;
                ldsm4(af[mt][0], af[mt][1], af[mt][2], af[mt][3], addr);
            }
            uint32_t bf[4][2];
            #pragma unroll
            for (int np = 0; np < 2; np++) {
                int n = warp_n * 32 + np * 16;
                uint32_t addr = sb + (uint32_t)((n + b_row) * PA + kc + b_col) * 2u;
                ldsm4(bf[np*2][0], bf[np*2][1], bf[np*2+1][0], bf[np*2+1][1], addr);
            }
            #pragma unroll
            for (int mt = 0; mt < 4; mt++)
                #pragma unroll
                for (int nt = 0; nt < 4; nt++)
                    mma_f16(acc[mt][nt], af[mt][0], af[mt][1], af[mt][2], af[mt][3],
                            bf[nt][0], bf[nt][1]);
        }
    }

    // ---- epilogue ----
    #pragma unroll
    for (int mt = 0; mt < 4; mt++) {
        #pragma unroll
        for (int nt = 0; nt < 4; nt++) {
            int r0 = bm + warp_m * 64 + mt * 16 + g;
            int cc = bn + warp_n * 32 + nt * 8 + tg * 2;
            #pragma unroll
            for (int half = 0; half < 2; half++) {
                int r = r0 + half * 8;
                float v0 = acc[mt][nt][half * 2 + 0];
                float v1 = acc[mt][nt][half * 2 + 1];
                size_t gix = (size_t)r * ldc + cc;
                float o0, o1;
                if (EPI == EPI_GATE) {
                    float gt0 = 1.f / (1.f + expf(-(v0 + bias[cc])));
                    float gt1 = 1.f / (1.f + expf(-(v1 + bias[cc + 1])));
                    o0 = gt0 * res0[gix]     + (1.f - gt0) * res1[gix];
                    o1 = gt1 * res0[gix + 1] + (1.f - gt1) * res1[gix + 1];
                } else if (EPI == EPI_SCALE) {
                    o0 = v0 * scale; o1 = v1 * scale;
                } else if (EPI == EPI_ADD) {
                    o0 = v0 + res0[gix]; o1 = v1 + res0[gix + 1];
                } else if (EPI == EPI_GELU) {
                    float x0 = v0 + bias[cc], x1 = v1 + bias[cc + 1];
                    o0 = 0.5f * x0 * (1.f + erff(x0 * 0.70710678118654752440f));
                    o1 = 0.5f * x1 * (1.f + erff(x1 * 0.70710678118654752440f));
                } else { // EPI_BIAS_RES
                    o0 = v0 + bias[cc]     + res0[gix];
                    o1 = v1 + bias[cc + 1] + res0[gix + 1];
                }
                if (EPI == EPI_GATE || EPI == EPI_ADD || EPI == EPI_BIAS_RES)
                    *reinterpret_cast<float2*>(&C[gix]) = make_float2(o0, o1);
                if (EPI == EPI_GATE || EPI == EPI_SCALE || EPI == EPI_GELU)
                    *reinterpret_cast<__half2*>(&Ch[gix]) = __floats2half2_rn(o0, o1);
            }
        }
    }
}

// ---------------------------------------------------------------------------
// fp32 -> fp16 elementwise convert (vectorized, 4 per thread)
// ---------------------------------------------------------------------------
__global__ void __launch_bounds__(256)
convert_h(const float* __restrict__ in, __half* __restrict__ out)
{
    size_t i4 = (size_t)blockIdx.x * 256 + threadIdx.x;
    float4 v = reinterpret_cast<const float4*>(in)[i4];
    reinterpret_cast<__half2*>(out)[i4 * 2]     = __floats2half2_rn(v.x, v.y);
    reinterpret_cast<__half2*>(out)[i4 * 2 + 1] = __floats2half2_rn(v.z, v.w);
}

// ---------------------------------------------------------------------------
// Tiled transpose + convert: out[c][r] = (half) in[r][c]
// ---------------------------------------------------------------------------
__global__ void __launch_bounds__(256)
transpose_h(const float* __restrict__ in, __half* __restrict__ out,
            int R, int C)
{
    __shared__ float t[32][33];
    in  += (size_t)blockIdx.z * R * C;
    out += (size_t)blockIdx.z * R * C;
    int r0 = blockIdx.y * 32, c0 = blockIdx.x * 32;
    int x = threadIdx.x, y = threadIdx.y;
    #pragma unroll
    for (int i = 0; i < 32; i += 8)
        t[y + i][x] = in[(size_t)(r0 + y + i) * C + c0 + x];
    __syncthreads();
    #pragma unroll
    for (int i = 0; i < 32; i += 8)
        out[(size_t)(c0 + y + i) * R + r0 + x] = __float2half_rn(t[x][y + i]);
}

// ---------------------------------------------------------------------------
// Warp helpers
// ---------------------------------------------------------------------------
__device__ __forceinline__ float warpMax(float v) {
    #pragma unroll
    for (int o = 16; o > 0; o >>= 1) v = fmaxf(v, __shfl_xor_sync(0xffffffffu, v, o));
    return v;
}
__device__ __forceinline__ float warpSum(float v) {
    #pragma unroll
    for (int o = 16; o > 0; o >>= 1) v += __shfl_xor_sync(0xffffffffu, v, o);
    return v;
}

// ---------------------------------------------------------------------------
// Row softmax over 2048 fp16 logits, in place (fp32 math inside)
// ---------------------------------------------------------------------------
__global__ void __launch_bounds__(256)
softmax_kernel(__half* __restrict__ S)
{
    __half* p = S + (size_t)blockIdx.x * SEQ;
    const int tid  = threadIdx.x;
    const int lane = tid & 31;
    const int wid  = tid >> 5;
    __shared__ float sh[8];

    // load 8 fp16 as 4 half2 (16B vector)
    __half2 hv[4];
    *reinterpret_cast<float4*>(hv) = *reinterpret_cast<const float4*>(&p[tid * 8]);
    float v[8];
    #pragma unroll
    for (int i = 0; i < 4; i++) {
        float2 f = __half22float2(hv[i]);
        v[i*2] = f.x; v[i*2+1] = f.y;
    }

    float m = v[0];
    #pragma unroll
    for (int i = 1; i < 8; i++) m = fmaxf(m, v[i]);
    m = warpMax(m);
    if (lane == 0) sh[wid] = m;
    __syncthreads();
    m = sh[0];
    #pragma unroll
    for (int w = 1; w < 8; w++) m = fmaxf(m, sh[w]);
    __syncthreads();

    float s = 0.f;
    #pragma unroll
    for (int i = 0; i < 8; i++) { v[i] = expf(v[i] - m); s += v[i]; }
    s = warpSum(s);
    if (lane == 0) sh[wid] = s;
    __syncthreads();
    float tot = sh[0];
    #pragma unroll
    for (int w = 1; w < 8; w++) tot += sh[w];
    float inv = 1.f / tot;

    #pragma unroll
    for (int i = 0; i < 4; i++)
        hv[i] = __floats2half2_rn(v[i*2] * inv, v[i*2+1] * inv);
    *reinterpret_cast<float4*>(&p[tid * 8]) = *reinterpret_cast<float4*>(hv);
}

// ---------------------------------------------------------------------------
// LayerNorm over last dim (512); optional fp16 companion output
// ---------------------------------------------------------------------------
__global__ void __launch_bounds__(128)
layernorm_kernel(const float* __restrict__ in, float* __restrict__ out,
                 __half* __restrict__ out_h,
                 const float* __restrict__ gamma, const float* __restrict__ beta)
{
    const size_t base = (size_t)blockIdx.x * DIM;
    const int tid  = threadIdx.x;
    const int lane = tid & 31;
    const int wid  = tid >> 5;
    __shared__ float shs[4], shq[4];

    float4 x = *reinterpret_cast<const float4*>(&in[base + tid * 4]);
    float s  = x.x + x.y + x.z + x.w;
    float ss = x.x * x.x + x.y * x.y + x.z * x.z + x.w * x.w;
    s  = warpSum(s);
    ss = warpSum(ss);
    if (lane == 0) { shs[wid] = s; shq[wid] = ss; }
    __syncthreads();
    float sum = shs[0] + shs[1] + shs[2] + shs[3];
    float sq  = shq[0] + shq[1] + shq[2] + shq[3];
    float mu  = sum * (1.f / DIM);
    float var = sq * (1.f / DIM) - mu * mu;
    float rs  = rsqrtf(var + 1e-5f);

    float4 gm = *reinterpret_cast<const float4*>(&gamma[tid * 4]);
    float4 bt = *reinterpret_cast<const float4*>(&beta[tid * 4]);
    float4 o;
    o.x = (x.x - mu) * rs * gm.x + bt.x;
    o.y = (x.y - mu) * rs * gm.y + bt.y;
    o.z = (x.z - mu) * rs * gm.z + bt.z;
    o.w = (x.w - mu) * rs * gm.w + bt.w;
    *reinterpret_cast<float4*>(&out[base + tid * 4]) = o;
    if (out_h) {
        *reinterpret_cast<__half2*>(&out_h[base + tid * 4])     = __floats2half2_rn(o.x, o.y);
        *reinterpret_cast<__half2*>(&out_h[base + tid * 4 + 2]) = __floats2half2_rn(o.z, o.w);
    }
}

// ---------------------------------------------------------------------------
// Launch
// ---------------------------------------------------------------------------
extern "C" void kernel_launch(void* const* d_in, const int* in_sizes, int n_in,
                              void* d_out, int out_size)
{
    const float* Noise = (const float*)d_in[0];
    const float* X     = (const float*)d_in[1];
    const float* cond  = (const float*)d_in[2];
    const float* Wg    = (const float*)d_in[3];
    const float* bg    = (const float*)d_in[4];
    const float* W1    = (const float*)d_in[5];
    const float* b1    = (const float*)d_in[6];
    const float* W2    = (const float*)d_in[7];
    const float* b2    = (const float*)d_in[8];
    const float* g1    = (const float*)d_in[9];
    const float* be1   = (const float*)d_in[10];
    const float* g2    = (const float*)d_in[11];
    const float* be2   = (const float*)d_in[12];
    float* out = (float*)d_out;

    float *fused, *q, *y;
    __half *fusedh, *attnh, *qh, *hh, *noiseh, *condh, *xh, *xth, *wgth, *w1th, *w2th;
    cudaGetSymbolAddress((void**)&fused,  g_fused);
    cudaGetSymbolAddress((void**)&q,      g_q);
    cudaGetSymbolAddress((void**)&y,      g_y);
    cudaGetSymbolAddress((void**)&fusedh, g_fusedh);
    cudaGetSymbolAddress((void**)&attnh,  g_attnh);
    cudaGetSymbolAddress((void**)&qh,     g_qh);
    cudaGetSymbolAddress((void**)&hh,     g_hh);
    cudaGetSymbolAddress((void**)&noiseh, g_noiseh);
    cudaGetSymbolAddress((void**)&condh,  g_condh);
    cudaGetSymbolAddress((void**)&xh,     g_xh);
    cudaGetSymbolAddress((void**)&xth,    g_xth);
    cudaGetSymbolAddress((void**)&wgth,   g_wgth);
    cudaGetSymbolAddress((void**)&w1th,   g_w1th);
    cudaGetSymbolAddress((void**)&w2th,   g_w2th);

    cudaFuncSetAttribute(gemm_mma<EPI_GATE, true>,      cudaFuncAttributeMaxDynamicSharedMemorySize, SMEM_BYTES_G);
    cudaFuncSetAttribute(gemm_mma<EPI_SCALE, false>,    cudaFuncAttributeMaxDynamicSharedMemorySize, SMEM_BYTES_G);
    cudaFuncSetAttribute(gemm_mma<EPI_ADD, false>,      cudaFuncAttributeMaxDynamicSharedMemorySize, SMEM_BYTES_G);
    cudaFuncSetAttribute(gemm_mma<EPI_GELU, false>,     cudaFuncAttributeMaxDynamicSharedMemorySize, SMEM_BYTES_G);
    cudaFuncSetAttribute(gemm_mma<EPI_BIAS_RES, false>, cudaFuncAttributeMaxDynamicSharedMemorySize, SMEM_BYTES_G);

    const float scale = 0.04419417382415922f;  // 1/sqrt(512)
    const int NEL = NTOK * DIM;

    // 0. fp16 conversions + transposes
    convert_h<<<NEL / 4 / 256, 256>>>(Noise, noiseh);
    convert_h<<<NEL / 4 / 256, 256>>>(cond,  condh);
    convert_h<<<NEL / 4 / 256, 256>>>(X,     xh);
    transpose_h<<<dim3(DIM / 32, 2 * DIM / 32, 1), dim3(32, 8)>>>(Wg, wgth, 2 * DIM, DIM);
    transpose_h<<<dim3(2 * DIM / 32, DIM / 32, 1), dim3(32, 8)>>>(W1, w1th, DIM, 2 * DIM);
    transpose_h<<<dim3(DIM / 32, 2 * DIM / 32, 1), dim3(32, 8)>>>(W2, w2th, 2 * DIM, DIM);
    transpose_h<<<dim3(DIM / 32, SEQ / 32, BATCH), dim3(32, 8)>>>(X, xth, SEQ, DIM);

    // 1. gate+fuse
    gemm_mma<EPI_GATE, true><<<dim3(DIM / BN, NTOK / BM, 1), NTHREADS, SMEM_BYTES_G>>>(
        noiseh, condh, wgth, fused, fusedh,
        2 * DIM, 2 * DIM, 2 * DIM, DIM,
        0, 0, 0, bg, Noise, cond, 0.f);

    // 2. logits = fused @ X^T * scale -> fp16 attnh
    gemm_mma<EPI_SCALE, false><<<dim3(SEQ / BN, SEQ / BM, BATCH), NTHREADS, SMEM_BYTES_G>>>(
        fusedh, nullptr, xh, nullptr, attnh,
        DIM, DIM, DIM, SEQ,
        (size_t)SEQ * DIM, (size_t)SEQ * DIM, (size_t)SEQ * SEQ,
        nullptr, nullptr, nullptr, scale);

    // 3. softmax in place (fp16)
    softmax_kernel<<<NTOK, 256>>>(attnh);

    // 4. fused += attn @ X
    gemm_mma<EPI_ADD, false><<<dim3(DIM / BN, SEQ / BM, BATCH), NTHREADS, SMEM_BYTES_G>>>(
        attnh, nullptr, xth, fused, nullptr,
        SEQ, SEQ, SEQ, DIM,
        (size_t)SEQ * SEQ, (size_t)DIM * SEQ, (size_t)SEQ * DIM,
        nullptr, fused, nullptr, 0.f);

    // 5. q = LN1(fused) (+ fp16)
    layernorm_kernel<<<NTOK, 128>>>(fused, q, qh, g1, be1);

    // 6. h = gelu(q @ W1 + b1) -> fp16
    gemm_mma<EPI_GELU, false><<<dim3(2 * DIM / BN, NTOK / BM, 1), NTHREADS, SMEM_BYTES_G>>>(
        qh, nullptr, w1th, nullptr, hh,
        DIM, DIM, DIM, 2 * DIM,
        0, 0, 0, b1, nullptr, nullptr, 0.f);

    // 7. y = h @ W2 + b2 + q
    gemm_mma<EPI_BIAS_RES, false><<<dim3(DIM / BN, NTOK / BM, 1), NTHREADS, SMEM_BYTES_G>>>(
        hh, nullptr, w2th, y, nullptr,
        2 * DIM, 2 * DIM, 2 * DIM, DIM,
        0, 0, 0, b2, q, nullptr, 0.f);

    // 8. out = LN2(y)
    layernorm_kernel<<<NTOK, 128>>>(y, out, nullptr, g2, be2);
}